// round 16
// baseline (speedup 1.0000x reference)
#include <cuda_runtime.h>
#include <cuda_bf16.h>
#include <cstdint>

// ---------------- problem constants ----------------
#define BATCH 32
#define NTOK  4096
#define FEAT  768
#define DIM   256
#define KVQ   256
#define NHEAD 4
#define DH    64
#define KSLOT 16
#define CHAN  64            // KSLOT * NHEAD
#define ITERS 3
#define EPSW  1e-8f
#define SCALE 0.125f        // DH^-0.5
#define MROWS (BATCH*NTOK)  // 131072
#define SPLITS 32           // attention N-splits (tokens per block = 128)
#define TOKCH 16            // tokens per attention smem tile

// GEMM config (mma.sync bf16, 3-term split via K-concat)
#define GBM 128
#define GBN 128
#define GBK 64
#define KEFF 2304
#define KSTAGES (KEFF/GBK)  // 36
#define GEMM_STAGE_BYTES 32768
#define GEMM_DSMEM (3*GEMM_STAGE_BYTES + 1024)   // 3-stage ring

// attn dynamic smem: ks 16*384 + vs 16*384 + wsum 8*9 + tots 8
#define ATTN_SM_FLOATS (2*TOKCH*384 + 8*9 + 8)
#define ATTN_DSMEM (ATTN_SM_FLOATS*4)

// ---------------- scratch (device globals; no allocation allowed) ----------------
__device__ __align__(16) __nv_bfloat16 g_a2[(size_t)MROWS*1536]; // [m][hi|lo]
__device__ __align__(16) __nv_bfloat16 g_b2[512*KEFF];           // [n][hi|lo|hi]
__device__ float g_wqt [256*256];            // fp32
// fp32 weights packed as float2 for wide loads (exact):
__device__ float2 g_wgru2[256*768];          // [cc][j][t]: j0=(wr,wz) j1=(wn,vr) j2=(vz,vn)
__device__ float2 g_wf1v [256*512];          // [cc][j][t]: j0=(w0,w1) j1=(w2,w3)
__device__ float2 g_wf2v [512*256];          // [j2][t]: (w_{2j2}, w_{2j2+1})
__device__ float g_kv  [(size_t)MROWS*512];  // per token: k[0:256] | v[256:512]
__device__ float g_q   [BATCH*KSLOT*256];
__device__ float g_slots[BATCH*KSLOT*256];
__device__ float g_vsp [BATCH*16*256];
__device__ float g_vsum[BATCH*256];
__device__ float g_Apart[BATCH*SPLITS*CHAN*DH];
__device__ float g_Spart[BATCH*SPLITS*CHAN];

// ---------------- PTX helpers ----------------
__device__ __forceinline__ uint32_t smem_u32(const void* p) {
    uint32_t a;
    asm("{ .reg .u64 t; cvta.to.shared.u64 t, %1; cvt.u32.u64 %0, t; }" : "=r"(a) : "l"(p));
    return a;
}
#define SWZ128(off) ((off) ^ (((off) >> 3) & 0x70))
#define CP16(dst, src) asm volatile("cp.async.cg.shared.global [%0], [%1], 16;" :: "r"(dst), "l"(src))
#define CP_COMMIT()    asm volatile("cp.async.commit_group;" ::: "memory")
#define CP_WAITG(n)    asm volatile("cp.async.wait_group %0;" :: "n"(n) : "memory")

#define LDSM4(R, addr) \
  asm volatile("ldmatrix.sync.aligned.m8n8.x4.shared.b16 {%0,%1,%2,%3}, [%4];" \
    : "=r"((R)[0]), "=r"((R)[1]), "=r"((R)[2]), "=r"((R)[3]) : "r"(addr))

#define MMA16816(C, A, B0, B1) \
  asm volatile("mma.sync.aligned.m16n8k16.row.col.f32.bf16.bf16.f32 " \
    "{%0,%1,%2,%3}, {%4,%5,%6,%7}, {%8,%9}, {%0,%1,%2,%3};" \
    : "+f"((C)[0]), "+f"((C)[1]), "+f"((C)[2]), "+f"((C)[3]) \
    : "r"((A)[0]), "r"((A)[1]), "r"((A)[2]), "r"((A)[3]), "r"(B0), "r"(B1))

// ---------------- generic helpers ----------------
__device__ __forceinline__ float2 blockReduce2(float a, float b, float* sh) {
    __syncthreads();
    #pragma unroll
    for (int off = 16; off; off >>= 1) {
        a += __shfl_xor_sync(0xffffffffu, a, off);
        b += __shfl_xor_sync(0xffffffffu, b, off);
    }
    int wid = threadIdx.x >> 5, lane = threadIdx.x & 31;
    if (lane == 0) { sh[wid*2] = a; sh[wid*2+1] = b; }
    __syncthreads();
    float ra = 0.f, rb = 0.f;
    #pragma unroll
    for (int w = 0; w < 8; w++) { ra += sh[w*2]; rb += sh[w*2+1]; }
    return make_float2(ra, rb);
}
// reduce over one 256-thread half of a 512-thread block (warps [half*8, half*8+8))
__device__ __forceinline__ float2 halfReduce2(float a, float b, float* sh) {
    __syncthreads();
    #pragma unroll
    for (int off = 16; off; off >>= 1) {
        a += __shfl_xor_sync(0xffffffffu, a, off);
        b += __shfl_xor_sync(0xffffffffu, b, off);
    }
    int wid = threadIdx.x >> 5, lane = threadIdx.x & 31;
    if (lane == 0) { sh[wid*2] = a; sh[wid*2+1] = b; }
    __syncthreads();
    int wbase = (threadIdx.x >> 8) * 8;
    float ra = 0.f, rb = 0.f;
    #pragma unroll
    for (int w = 0; w < 8; w++) { ra += sh[(wbase+w)*2]; rb += sh[(wbase+w)*2+1]; }
    return make_float2(ra, rb);
}
__device__ __forceinline__ float sigmoidf_(float x) { return 1.0f / (1.0f + __expf(-x)); }
__device__ __forceinline__ float gelu_exact(float x) { return 0.5f * x * (1.0f + erff(x * 0.70710678118654752f)); }
__device__ __forceinline__ float rcp_fast(float x) { float r; asm("rcp.approx.f32 %0, %1;" : "=f"(r) : "f"(x)); return r; }

// ---------------- prep A: split-bf16 B for the kv GEMM ----------------
__global__ void prep_a_kernel(const float* __restrict__ kw, const float* __restrict__ vw) {
    int idx = blockIdx.x * blockDim.x + threadIdx.x;
    int stride = gridDim.x * blockDim.x;
    for (int p = idx; p < 512*KEFF; p += stride) {
        int n = p / KEFF, kk = p - n*KEFF;
        int k = (kk < 768) ? kk : ((kk < 1536) ? kk - 768 : kk - 1536);
        float src = (n < 256) ? kw[n*768 + k] : vw[(n-256)*768 + k];
        __nv_bfloat16 h = __float2bfloat16(src);
        if (kk >= 768 && kk < 1536) h = __float2bfloat16(src - __bfloat162float(h));
        g_b2[p] = h;
    }
}

// ---------------- prep B: float2-packed fp32 update weights + wqt + slots --------
__global__ void prep_b_kernel(const float* __restrict__ wih, const float* __restrict__ whh,
                              const float* __restrict__ f1, const float* __restrict__ f2,
                              const float* __restrict__ qw, const float* __restrict__ cond) {
    int idx = blockIdx.x * blockDim.x + threadIdx.x;
    int stride = gridDim.x * blockDim.x;
    for (int p = idx; p < 256*768; p += stride) {
        int cc = p / 768, rem = p - cc*768;
        int j = rem >> 8, t = rem & 255;
        float2 u;
        if (j == 0)      u = make_float2(wih[t*256 + cc],       wih[(256+t)*256 + cc]);
        else if (j == 1) u = make_float2(wih[(512+t)*256 + cc], whh[t*256 + cc]);
        else             u = make_float2(whh[(256+t)*256 + cc], whh[(512+t)*256 + cc]);
        g_wgru2[p] = u;
    }
    for (int p = idx; p < 256*512; p += stride) {
        int cc = p >> 9, rem = p & 511;
        int j = rem >> 8, t = rem & 255;
        float2 u = (j == 0) ? make_float2(f1[t*256 + cc],       f1[(256+t)*256 + cc])
                            : make_float2(f1[(512+t)*256 + cc], f1[(768+t)*256 + cc]);
        g_wf1v[p] = u;
    }
    for (int p = idx; p < 512*256; p += stride) {
        int j2 = p >> 8, t = p & 255;
        g_wf2v[p] = make_float2(f2[t*1024 + 2*j2], f2[t*1024 + 2*j2 + 1]);
    }
    for (int p = idx; p < 256*256; p += stride)  g_wqt[p] = qw[(p & 255)*256 + (p >> 8)];
    for (int p = idx; p < BATCH*KSLOT*256; p += stride) g_slots[p] = cond[p];
}

// ---------------- fused input LN+convert AND iter-0 qproj ----------------
__global__ __launch_bounds__(256) void lnq_kernel(const float* __restrict__ x,
                                                  const float* __restrict__ lng,
                                                  const float* __restrict__ lnb,
                                                  const float* __restrict__ cond,
                                                  const float* __restrict__ slng,
                                                  const float* __restrict__ slnb) {
    __shared__ float sh[16];
    __shared__ float s_ln[256];
    int t = threadIdx.x;
    if (blockIdx.x < MROWS) {
        size_t row = blockIdx.x;
        const float* xr = x + row * FEAT;
        float v0 = xr[t], v1 = xr[t+256], v2 = xr[t+512];
        float2 r = blockReduce2(v0+v1+v2, v0*v0 + v1*v1 + v2*v2, sh);
        float m = r.x * (1.0f/768.0f);
        float var = r.y * (1.0f/768.0f) - m*m;
        float rs = rsqrtf(var + 1e-5f);
        __nv_bfloat16* dst = g_a2 + row * 1536;
        float vv[3] = {v0, v1, v2};
        #pragma unroll
        for (int i = 0; i < 3; i++) {
            int col = t + i*256;
            float val = (vv[i] - m)*rs*lng[col] + lnb[col];
            __nv_bfloat16 hi = __float2bfloat16(val);
            __nv_bfloat16 lo = __float2bfloat16(val - __bfloat162float(hi));
            dst[col] = hi;
            dst[768 + col] = lo;
        }
    } else {
        int bi = blockIdx.x - MROWS;
        float xv = cond[(size_t)bi*256 + t];
        float2 r = blockReduce2(xv, xv*xv, sh);
        float m = r.x * (1.0f/256.0f);
        float var = r.y * (1.0f/256.0f) - m*m;
        float rs = rsqrtf(var + 1e-5f);
        s_ln[t] = (xv - m)*rs*slng[t] + slnb[t];
        __syncthreads();
        float acc = 0.f;
        for (int c = 0; c < 256; c++) acc += s_ln[c] * g_wqt[c*256 + t];
        g_q[(size_t)bi*256 + t] = acc;
    }
}

// ---------------- k|v projection GEMM via mma.sync bf16, 3-stage cp.async ring ----
__device__ __forceinline__ void gemm_load_stage(int tid, int m0, int bn0, int ks, uint32_t sbase) {
    int kk = ks * GBK;
    int ka = (kk < 768) ? kk : kk - 768;
    uint32_t sA = sbase;
    uint32_t sB = sbase + 16384;
    #pragma unroll
    for (int i = 0; i < 4; i++) {
        int c = tid + i*256;
        int row = c >> 3, seg = c & 7;
        const char* src = (const char*)g_a2 + ((size_t)(m0+row)*1536 + ka)*2 + seg*16;
        CP16(sA + SWZ128((uint32_t)(row*128 + seg*16)), src);
    }
    #pragma unroll
    for (int i = 0; i < 4; i++) {
        int c = tid + i*256;
        int row = c >> 3, seg = c & 7;
        const char* src = (const char*)g_b2 + ((size_t)(bn0+row)*KEFF + kk)*2 + seg*16;
        CP16(sB + SWZ128((uint32_t)(row*128 + seg*16)), src);
    }
}

__global__ __launch_bounds__(256, 2) void gemm_kv_mma() {
    extern __shared__ char dynsm[];
    uint32_t sbase = (smem_u32(dynsm) + 1023u) & ~1023u;
    const int tid = threadIdx.x;
    const int wid = tid >> 5, lane = tid & 31;
    const int m0  = blockIdx.y * GBM;
    const int bn0 = blockIdx.x * GBN;
    const int wm = wid >> 1, wn = wid & 1;

    float acc[2][8][4];
    #pragma unroll
    for (int a = 0; a < 2; a++)
        #pragma unroll
        for (int b = 0; b < 8; b++)
            #pragma unroll
            for (int c = 0; c < 4; c++) acc[a][b][c] = 0.f;

    gemm_load_stage(tid, m0, bn0, 0, sbase);
    CP_COMMIT();
    gemm_load_stage(tid, m0, bn0, 1, sbase + GEMM_STAGE_BYTES);
    CP_COMMIT();

    const int a_row = wm*32 + (lane & 15);
    const int a_col = (lane >> 4) << 4;
    const int b_g = lane >> 3, b_r = lane & 7;
    const int b_row_in = ((b_g >> 1) << 3) + b_r;
    const int b_col = (b_g & 1) << 4;

    int cur = 0;
    for (int ks = 0; ks < KSTAGES; ks++) {
        if (ks + 1 < KSTAGES) { CP_WAITG(1); } else { CP_WAITG(0); }
        __syncthreads();
        if (ks + 2 < KSTAGES) {
            int nxt = cur + 2; if (nxt >= 3) nxt -= 3;
            gemm_load_stage(tid, m0, bn0, ks + 2, sbase + nxt * GEMM_STAGE_BYTES);
            CP_COMMIT();
        }
        uint32_t sA = sbase + cur * GEMM_STAGE_BYTES;
        uint32_t sB = sA + 16384;
        #pragma unroll
        for (int k16 = 0; k16 < 4; k16++) {
            uint32_t afr[2][4], bfr[4][4];
            #pragma unroll
            for (int mt = 0; mt < 2; mt++) {
                uint32_t addr = sA + SWZ128((uint32_t)((a_row + mt*16)*128 + k16*32 + a_col));
                LDSM4(afr[mt], addr);
            }
            #pragma unroll
            for (int p = 0; p < 4; p++) {
                uint32_t addr = sB + SWZ128((uint32_t)((wn*64 + p*16 + b_row_in)*128 + k16*32 + b_col));
                LDSM4(bfr[p], addr);
            }
            #pragma unroll
            for (int mt = 0; mt < 2; mt++)
                #pragma unroll
                for (int nt = 0; nt < 8; nt++) {
                    int p = nt >> 1, h = nt & 1;
                    MMA16816(acc[mt][nt], afr[mt], bfr[p][h*2], bfr[p][h*2+1]);
                }
        }
        cur++; if (cur >= 3) cur = 0;
    }

    int quad = lane >> 2, qid = lane & 3;
    #pragma unroll
    for (int mt = 0; mt < 2; mt++)
        #pragma unroll
        for (int nt = 0; nt < 8; nt++) {
            int mrow = m0 + wm*32 + mt*16 + quad;
            int col  = bn0 + wn*64 + nt*8 + qid*2;
            *(float2*)(g_kv + (size_t)mrow*512 + col)     = make_float2(acc[mt][nt][0], acc[mt][nt][1]);
            *(float2*)(g_kv + (size_t)(mrow+8)*512 + col) = make_float2(acc[mt][nt][2], acc[mt][nt][3]);
        }
}

// ---------------- vsum ----------------
__global__ __launch_bounds__(256) void vsum_part_kernel() {
    int b = blockIdx.y, sp = blockIdx.x;
    int t = threadIdx.x;
    float s = 0.f;
    int j0 = sp * 256;
    for (int j = 0; j < 256; j++)
        s += g_kv[((size_t)(b*NTOK + j0 + j))*512 + 256 + t];
    g_vsp[(b*16+sp)*256 + t] = s;
}
__global__ __launch_bounds__(256) void vsum_reduce_kernel() {
    int b = blockIdx.x, t = threadIdx.x;
    float s = 0.f;
    for (int sp = 0; sp < 16; sp++) s += g_vsp[(b*16+sp)*256 + t];
    g_vsum[b*256 + t] = s;
}

// ---------------- slot LN + q projection (iters >= 1) ----------------
__global__ __launch_bounds__(256) void qproj_kernel(const float* __restrict__ lng,
                                                    const float* __restrict__ lnb) {
    __shared__ float s_ln[256];
    __shared__ float sh[16];
    int t = threadIdx.x;
    int bi = blockIdx.x;
    float xv = g_slots[(size_t)bi*256 + t];
    float2 r = blockReduce2(xv, xv*xv, sh);
    float m = r.x * (1.0f/256.0f);
    float var = r.y * (1.0f/256.0f) - m*m;
    float rs = rsqrtf(var + 1e-5f);
    s_ln[t] = (xv - m)*rs*lng[t] + lnb[t];
    __syncthreads();
    float acc = 0.f;
    for (int c = 0; c < 256; c++) acc += s_ln[c] * g_wqt[c*256 + t];
    g_q[(size_t)bi*256 + t] = acc;
}

// ---------------- attention pass (2 ch/thread, 8-float d-slices, 8-token softmax) -
__global__ __launch_bounds__(256, 3) void attn_kernel(float* __restrict__ attn_out, int lastIter) {
    extern __shared__ float dsm[];
    float* ksp  = dsm;
    float* vsp  = dsm + TOKCH*384;
    float* wsum = dsm + 2*TOKCH*384;
    float* tots = wsum + 8*9;

    int b = blockIdx.y, sp = blockIdx.x;
    int tid = threadIdx.x;
    int lane = tid & 31, wid = tid >> 5;
    int cg  = tid >> 3;
    int qd8 = tid & 7;
    int h   = cg & 3;
    int koff = (h*8 + qd8) * 12;

    // q pre-scaled by SCALE (folds softmax scale into the dot)
    float4 ql0, ql1, qh0, qh1;
    {
        const float* qp = g_q + (size_t)b*4096 + cg*64 + qd8*8;
        ql0 = *(const float4*)qp;        ql1 = *(const float4*)(qp + 4);
        qh0 = *(const float4*)(qp+2048); qh1 = *(const float4*)(qp + 2052);
        ql0.x*=SCALE; ql0.y*=SCALE; ql0.z*=SCALE; ql0.w*=SCALE;
        ql1.x*=SCALE; ql1.y*=SCALE; ql1.z*=SCALE; ql1.w*=SCALE;
        qh0.x*=SCALE; qh0.y*=SCALE; qh0.z*=SCALE; qh0.w*=SCALE;
        qh1.x*=SCALE; qh1.y*=SCALE; qh1.z*=SCALE; qh1.w*=SCALE;
    }

    float accA_lo[8] = {}, accA_hi[8] = {};
    float accS_lo = 0.f, accS_hi = 0.f;
    int j0base = sp * (NTOK/SPLITS);

    for (int ch = 0; ch < (NTOK/SPLITS)/TOKCH; ch++) {
        __syncthreads();
        int j0 = j0base + ch*TOKCH;
        #pragma unroll
        for (int it = 0; it < 8; it++) {
            int idx = tid + it*256;
            int r = idx >> 7, w4 = idx & 127;
            float4 v4 = *(const float4*)(g_kv + ((size_t)(b*NTOK + j0 + r))*512 + w4*4);
            int wl = w4 & 63;
            uint32_t off = r*384 + (wl >> 1)*12 + (wl & 1)*4;
            if (w4 < 64) *(float4*)&ksp[off] = v4;
            else         *(float4*)&vsp[off] = v4;
        }
        __syncthreads();

        #pragma unroll
        for (int g = 0; g < 2; g++) {
            int rbase = g*8;
            float e_lo[8], e_hi[8];
            #pragma unroll
            for (int r = 0; r < 8; r++) {
                const float* kp = &ksp[(rbase + r)*384 + koff];
                float4 k0 = *(const float4*)kp;
                float4 k1 = *(const float4*)(kp + 4);
                float pl = ql0.x*k0.x + ql0.y*k0.y + ql0.z*k0.z + ql0.w*k0.w
                         + ql1.x*k1.x + ql1.y*k1.y + ql1.z*k1.z + ql1.w*k1.w;
                float ph = qh0.x*k0.x + qh0.y*k0.y + qh0.z*k0.z + qh0.w*k0.w
                         + qh1.x*k1.x + qh1.y*k1.y + qh1.z*k1.z + qh1.w*k1.w;
                pl += __shfl_xor_sync(0xffffffffu, pl, 1);
                ph += __shfl_xor_sync(0xffffffffu, ph, 1);
                pl += __shfl_xor_sync(0xffffffffu, pl, 2);
                ph += __shfl_xor_sync(0xffffffffu, ph, 2);
                pl += __shfl_xor_sync(0xffffffffu, pl, 4);
                ph += __shfl_xor_sync(0xffffffffu, ph, 4);
                float el = __expf(pl);
                float eh = __expf(ph);
                e_lo[r] = el; e_hi[r] = eh;
                float cs = el + eh;
                cs += __shfl_xor_sync(0xffffffffu, cs, 8);
                cs += __shfl_xor_sync(0xffffffffu, cs, 16);
                if (lane == 0) wsum[wid*9 + r] = cs;
            }
            __syncthreads();
            if (tid < 64) {
                int rr = tid >> 3, ww = tid & 7;
                float vsm = wsum[ww*9 + rr];
                vsm += __shfl_xor_sync(0xffffffffu, vsm, 1);
                vsm += __shfl_xor_sync(0xffffffffu, vsm, 2);
                vsm += __shfl_xor_sync(0xffffffffu, vsm, 4);
                if (ww == 0) tots[rr] = rcp_fast(vsm);
            }
            __syncthreads();
            #pragma unroll
            for (int r = 0; r < 8; r++) {
                float rt = tots[r];
                float alo = e_lo[r] * rt;
                float ahi = e_hi[r] * rt;
                accS_lo += alo; accS_hi += ahi;
                const float* vp = &vsp[(rbase + r)*384 + koff];
                float4 v0 = *(const float4*)vp;
                float4 v1 = *(const float4*)(vp + 4);
                accA_lo[0] += alo*v0.x; accA_lo[1] += alo*v0.y; accA_lo[2] += alo*v0.z; accA_lo[3] += alo*v0.w;
                accA_lo[4] += alo*v1.x; accA_lo[5] += alo*v1.y; accA_lo[6] += alo*v1.z; accA_lo[7] += alo*v1.w;
                accA_hi[0] += ahi*v0.x; accA_hi[1] += ahi*v0.y; accA_hi[2] += ahi*v0.z; accA_hi[3] += ahi*v0.w;
                accA_hi[4] += ahi*v1.x; accA_hi[5] += ahi*v1.y; accA_hi[6] += ahi*v1.z; accA_hi[7] += ahi*v1.w;
                if (lastIter) {
                    float aol = alo + __shfl_xor_sync(0xffffffffu, alo, 8);
                    float aoh = ahi + __shfl_xor_sync(0xffffffffu, ahi, 8);
                    aol += __shfl_xor_sync(0xffffffffu, aol, 16);
                    aoh += __shfl_xor_sync(0xffffffffu, aoh, 16);
                    if (lane == 0) {
                        attn_out[((size_t)(b*KSLOT + wid))*NTOK + j0 + rbase + r]     = aol * 0.25f;
                        attn_out[((size_t)(b*KSLOT + wid + 8))*NTOK + j0 + rbase + r] = aoh * 0.25f;
                    }
                }
            }
        }
    }
    size_t base_lo = ((size_t)((b*SPLITS + sp)*CHAN + cg))*DH + qd8*8;
    size_t base_hi = ((size_t)((b*SPLITS + sp)*CHAN + cg + 32))*DH + qd8*8;
    *(float4*)(g_Apart + base_lo)     = make_float4(accA_lo[0], accA_lo[1], accA_lo[2], accA_lo[3]);
    *(float4*)(g_Apart + base_lo + 4) = make_float4(accA_lo[4], accA_lo[5], accA_lo[6], accA_lo[7]);
    *(float4*)(g_Apart + base_hi)     = make_float4(accA_hi[0], accA_hi[1], accA_hi[2], accA_hi[3]);
    *(float4*)(g_Apart + base_hi + 4) = make_float4(accA_hi[4], accA_hi[5], accA_hi[6], accA_hi[7]);
    if (qd8 == 0) {
        g_Spart[(b*SPLITS + sp)*CHAN + cg]      = accS_lo;
        g_Spart[(b*SPLITS + sp)*CHAN + cg + 32] = accS_hi;
    }
}

// ---------------- update: 512 threads, slot-split halves (2 slots per half) -------
__global__ __launch_bounds__(512) void update_kernel(
        const float* __restrict__ gbih, const float* __restrict__ gbhh,
        const float* __restrict__ ffg, const float* __restrict__ ffb,
        const float* __restrict__ fb1, const float* __restrict__ fb2,
        float* __restrict__ out_slots, int last) {
    __shared__ float u4 [4][256];
    __shared__ float h4 [4][256];
    __shared__ float hn4[4][256];
    __shared__ float ln4[4][256];
    __shared__ float h1s[4][1024];
    __shared__ float sh[32];
    int t = threadIdx.x;
    int th = t & 255, half = t >> 8;
    int base = blockIdx.x * 4;
    int b = base >> 4;
    int hh = th >> 6, d = th & 63;
    float vsm = g_vsum[b*256 + th];
    #pragma unroll
    for (int sl = 0; sl < 2; sl++) {
        int s = half*2 + sl;
        int i = (base + s) & 15;
        int c = i*NHEAD + hh;
        float A = 0.f, S0 = 0.f;
        #pragma unroll
        for (int sp = 0; sp < SPLITS; sp++) {
            A  += g_Apart[((size_t)((b*SPLITS+sp)*CHAN + c))*DH + d];
            S0 += g_Spart[(b*SPLITS+sp)*CHAN + c];
        }
        float S = S0 + (float)NTOK * EPSW;
        u4[s][th] = (A + EPSW * vsm) / S;
        h4[s][th] = g_slots[(size_t)(base+s)*256 + th];
    }
    __syncthreads();
    // GRU: each half handles its 2 slots over all 256 cc
    float gir[2] = {}, giz[2] = {}, gin[2] = {};
    float ghr[2] = {}, ghz[2] = {}, ghn[2] = {};
    for (int cc = 0; cc < 256; cc++) {
        float2 p0 = g_wgru2[cc*768 + th];
        float2 p1 = g_wgru2[cc*768 + 256 + th];
        float2 p2 = g_wgru2[cc*768 + 512 + th];
        float wr = p0.x, wz = p0.y;
        float wn = p1.x, vr = p1.y;
        float vz = p2.x, vn = p2.y;
        #pragma unroll
        for (int sl = 0; sl < 2; sl++) {
            int s = half*2 + sl;
            float xv = u4[s][cc], hv = h4[s][cc];
            gir[sl] += wr*xv; giz[sl] += wz*xv; gin[sl] += wn*xv;
            ghr[sl] += vr*hv; ghz[sl] += vz*hv; ghn[sl] += vn*hv;
        }
    }
    float bir = gbih[th], biz = gbih[256+th], bin = gbih[512+th];
    float bhr = gbhh[th], bhz = gbhh[256+th], bhn = gbhh[512+th];
    #pragma unroll
    for (int sl = 0; sl < 2; sl++) {
        int s = half*2 + sl;
        float r = sigmoidf_(gir[sl] + bir + ghr[sl] + bhr);
        float z = sigmoidf_(giz[sl] + biz + ghz[sl] + bhz);
        float n = tanhf(gin[sl] + bin + r*(ghn[sl] + bhn));
        hn4[s][th] = (1.0f - z)*n + z*h4[s][th];
    }
    __syncthreads();
    // LN per slot: each half reduces its 2 slots
    #pragma unroll
    for (int sl = 0; sl < 2; sl++) {
        int s = half*2 + sl;
        float v = hn4[s][th];
        float2 r = halfReduce2(v, v*v, sh);
        float m = r.x * (1.0f/256.0f);
        float var = r.y * (1.0f/256.0f) - m*m;
        float rs = rsqrtf(var + 1e-5f);
        ln4[s][th] = (v - m)*rs*ffg[th] + ffb[th];
    }
    __syncthreads();
    // FF1 + gelu: each half its 2 slots
    float a1[2][4] = {};
    for (int cc = 0; cc < 256; cc++) {
        float2 p0 = g_wf1v[cc*512 + th];
        float2 p1 = g_wf1v[cc*512 + 256 + th];
        float w0 = p0.x, w1 = p0.y;
        float w2 = p1.x, w3 = p1.y;
        #pragma unroll
        for (int sl = 0; sl < 2; sl++) {
            float xv = ln4[half*2 + sl][cc];
            a1[sl][0] += w0*xv; a1[sl][1] += w1*xv; a1[sl][2] += w2*xv; a1[sl][3] += w3*xv;
        }
    }
    #pragma unroll
    for (int sl = 0; sl < 2; sl++) {
        int s = half*2 + sl;
        #pragma unroll
        for (int q = 0; q < 4; q++) {
            int row = q*256 + th;
            h1s[s][row] = gelu_exact(a1[sl][q] + fb1[row]);
        }
    }
    __syncthreads();
    // FF2 + residual: each half its 2 slots
    float o[2];
    #pragma unroll
    for (int sl = 0; sl < 2; sl++) o[sl] = hn4[half*2 + sl][th] + fb2[th];
    for (int j2 = 0; j2 < 512; j2++) {
        float2 p = g_wf2v[j2*256 + th];
        #pragma unroll
        for (int sl = 0; sl < 2; sl++)
            o[sl] += p.x * h1s[half*2 + sl][2*j2] + p.y * h1s[half*2 + sl][2*j2 + 1];
    }
    #pragma unroll
    for (int sl = 0; sl < 2; sl++) {
        int s = half*2 + sl;
        g_slots[(size_t)(base+s)*256 + th] = o[sl];
        if (last) out_slots[(size_t)(base+s)*256 + th] = o[sl];
    }
}

// ---------------- launch ----------------
extern "C" void kernel_launch(void* const* d_in, const int* in_sizes, int n_in,
                              void* d_out, int out_size) {
    const float* inputs   = (const float*)d_in[0];
    const float* cond     = (const float*)d_in[1];
    const float* to_q_w   = (const float*)d_in[2];
    const float* to_k_w   = (const float*)d_in[3];
    const float* to_v_w   = (const float*)d_in[4];
    const float* gru_w_ih = (const float*)d_in[5];
    const float* gru_w_hh = (const float*)d_in[6];
    const float* gru_b_ih = (const float*)d_in[7];
    const float* gru_b_hh = (const float*)d_in[8];
    const float* ln_in_g  = (const float*)d_in[9];
    const float* ln_in_b  = (const float*)d_in[10];
    const float* ln_sl_g  = (const float*)d_in[11];
    const float* ln_sl_b  = (const float*)d_in[12];
    const float* ff_ln_g  = (const float*)d_in[13];
    const float* ff_ln_b  = (const float*)d_in[14];
    const float* ff_w1    = (const float*)d_in[15];
    const float* ff_b1    = (const float*)d_in[16];
    const float* ff_w2    = (const float*)d_in[17];
    const float* ff_b2    = (const float*)d_in[18];
    float* out = (float*)d_out;
    float* out_attn = out + BATCH*KSLOT*256;   // slots first, then attn_out

    cudaFuncSetAttribute(gemm_kv_mma, cudaFuncAttributeMaxDynamicSharedMemorySize, GEMM_DSMEM);
    cudaFuncSetAttribute(attn_kernel, cudaFuncAttributeMaxDynamicSharedMemorySize, ATTN_DSMEM);

    prep_a_kernel<<<1024, 256>>>(to_k_w, to_v_w);                                               // 0
    prep_b_kernel<<<512, 256>>>(gru_w_ih, gru_w_hh, ff_w1, ff_w2, to_q_w, cond);                // 1
    lnq_kernel<<<MROWS + BATCH*KSLOT, 256>>>(inputs, ln_in_g, ln_in_b, cond, ln_sl_g, ln_sl_b); // 2
    gemm_kv_mma<<<dim3(512/GBN, MROWS/GBM), 256, GEMM_DSMEM>>>();                               // 3 (ncu slot)
    attn_kernel<<<dim3(SPLITS, BATCH), 256, ATTN_DSMEM>>>(out_attn, 0);                         // 4
    vsum_part_kernel<<<dim3(16, BATCH), 256>>>();                                               // 5
    vsum_reduce_kernel<<<BATCH, 256>>>();                                                       // 6
    update_kernel<<<BATCH*KSLOT/4, 512>>>(gru_b_ih, gru_b_hh, ff_ln_g, ff_ln_b,
                                          ff_b1, ff_b2, out, 0);                                // 7

    for (int it = 1; it < ITERS; it++) {
        int last = (it == ITERS - 1) ? 1 : 0;
        qproj_kernel<<<BATCH*KSLOT, 256>>>(ln_sl_g, ln_sl_b);
        attn_kernel<<<dim3(SPLITS, BATCH), 256, ATTN_DSMEM>>>(out_attn, last);
        update_kernel<<<BATCH*KSLOT/4, 512>>>(gru_b_ih, gru_b_hh, ff_ln_g, ff_ln_b,
                                              ff_b1, ff_b2, out, last);
    }
}